// round 16
// baseline (speedup 1.0000x reference)
#include <cuda_runtime.h>
#include <cstdint>

#define SS   2048
#define DD   1024
#define NH   16
#define HDIM 64
#define NBINS 8192
#define CCAP  32768
#define RANK0 3984587

// candidate window: bins [WLO_BIN, WHI_BIN) ~ scores in [0.55, 0.80)
#define WLO_BIN 4659
#define WHI_BIN 4916
#define WLO_F   (WLO_BIN * 0.0009765625f)   // exact fp32
#define WHI_F   (WHI_BIN * 0.0009765625f)   // exact fp32
#define WCAP    524288                       // per-head global window buffer cap

#define BM 128
#define BN 128
#define BK 16
#define TM 8
#define TN 8

// ---------------- scratch ----------------
__device__ float g_q[SS * DD];
__device__ float g_k[SS * DD];
__device__ float g_v[SS * DD];
__device__ float g_o[SS * DD];
__device__ float g_scores[(size_t)NH * SS * SS];   // 256 MB
__device__ unsigned g_hist[NH * NBINS];
__device__ float g_thr[NH];
__device__ float g_wcand[(size_t)NH * WCAP];       // 32 MB window buffer
__device__ int g_wcnt[NH];
__device__ int g_wover[NH];

__device__ __forceinline__ float inf_f() { return __int_as_float(0x7f800000); }

// 8192 bins over [-4,4): width 1/1024. Scores ~N(0,0.41): clamp bins empty.
// Note: (v+4)*1024 has exact x1024, so bin(v) in [a,b) <=> fl(v+4) in [a/1024,b/1024).
__device__ __forceinline__ int score_bin(float v) {
    int b = __float2int_rd((v + 4.0f) * 1024.0f);
    return min(max(b, 0), NBINS - 1);
}

// ---------------- K0: zero per-launch state ----------------
__global__ void zero_kernel() {
    int i = blockIdx.x * blockDim.x + threadIdx.x;
    if (i < NH * NBINS) g_hist[i] = 0;
    if (i < NH) { g_wcnt[i] = 0; g_wover[i] = 0; }
}

// ---------------- double-buffered fp32 GEMM mainloop ----------------
template<int KTOT, bool BT>
__device__ __forceinline__ void gemm_mainloop(
    const float* __restrict__ A, int lda,
    const float* __restrict__ Bm, int ldb,
    int bm, int bn, float acc[TM][TN])
{
    __shared__ float As[2][BK][BM];
    __shared__ float Bs[2][BK][BN];
    const int tid = threadIdx.x;
    const int tr = (tid >> 4) * TM;
    const int tc = (tid & 15) * TN;

    const int ar0 = tid >> 2;           // 0..63
    const int ar1 = ar0 + 64;           // 64..127
    const int ac  = (tid & 3) * 4;      // 0,4,8,12
    const int br0 = tid >> 5;           // 0..7
    const int br1 = br0 + 8;
    const int bc  = (tid & 31) * 4;

    float4 pa0, pa1, pb0, pb1;

    auto loadT = [&](int k0) {
        pa0 = *(const float4*)&A[(size_t)(bm + ar0) * lda + k0 + ac];
        pa1 = *(const float4*)&A[(size_t)(bm + ar1) * lda + k0 + ac];
        if (BT) {
            pb0 = *(const float4*)&Bm[(size_t)(bn + ar0) * ldb + k0 + ac];
            pb1 = *(const float4*)&Bm[(size_t)(bn + ar1) * ldb + k0 + ac];
        } else {
            pb0 = *(const float4*)&Bm[(size_t)(k0 + br0) * ldb + bn + bc];
            pb1 = *(const float4*)&Bm[(size_t)(k0 + br1) * ldb + bn + bc];
        }
    };
    auto storeT = [&](int buf) {
        As[buf][ac + 0][ar0] = pa0.x; As[buf][ac + 1][ar0] = pa0.y;
        As[buf][ac + 2][ar0] = pa0.z; As[buf][ac + 3][ar0] = pa0.w;
        As[buf][ac + 0][ar1] = pa1.x; As[buf][ac + 1][ar1] = pa1.y;
        As[buf][ac + 2][ar1] = pa1.z; As[buf][ac + 3][ar1] = pa1.w;
        if (BT) {
            Bs[buf][ac + 0][ar0] = pb0.x; Bs[buf][ac + 1][ar0] = pb0.y;
            Bs[buf][ac + 2][ar0] = pb0.z; Bs[buf][ac + 3][ar0] = pb0.w;
            Bs[buf][ac + 0][ar1] = pb1.x; Bs[buf][ac + 1][ar1] = pb1.y;
            Bs[buf][ac + 2][ar1] = pb1.z; Bs[buf][ac + 3][ar1] = pb1.w;
        } else {
            *(float4*)&Bs[buf][br0][bc] = pb0;
            *(float4*)&Bs[buf][br1][bc] = pb1;
        }
    };

    loadT(0);
    storeT(0);
    __syncthreads();
    const int NIT = KTOT / BK;
    for (int it = 0; it < NIT; ++it) {
        int buf = it & 1;
        if (it + 1 < NIT) loadT((it + 1) * BK);
#pragma unroll
        for (int kk = 0; kk < BK; ++kk) {
            float4 a0 = *(const float4*)&As[buf][kk][tr];
            float4 a1 = *(const float4*)&As[buf][kk][tr + 4];
            float4 b0 = *(const float4*)&Bs[buf][kk][tc];
            float4 b1 = *(const float4*)&Bs[buf][kk][tc + 4];
            float af[TM] = {a0.x, a0.y, a0.z, a0.w, a1.x, a1.y, a1.z, a1.w};
            float bf[TN] = {b0.x, b0.y, b0.z, b0.w, b1.x, b1.y, b1.z, b1.w};
#pragma unroll
            for (int i = 0; i < TM; i++)
#pragma unroll
                for (int j = 0; j < TN; j++)
                    acc[i][j] += af[i] * bf[j];
        }
        if (it + 1 < NIT) storeT(buf ^ 1);
        __syncthreads();
    }
}

// ---------------- K1: fused QKV projection ----------------
__global__ __launch_bounds__(256, 2) void qkv_kernel(
    const float* __restrict__ x,
    const float* __restrict__ Wq, const float* __restrict__ bq,
    const float* __restrict__ Wk, const float* __restrict__ bk,
    const float* __restrict__ Wv, const float* __restrict__ bv,
    float* __restrict__ q, float* __restrict__ k, float* __restrict__ v)
{
    const float* W; const float* bias; float* C;
    if (blockIdx.z == 0)      { W = Wq; bias = bq; C = q; }
    else if (blockIdx.z == 1) { W = Wk; bias = bk; C = k; }
    else                      { W = Wv; bias = bv; C = v; }

    int bm = blockIdx.y * BM, bn = blockIdx.x * BN;
    int tid = threadIdx.x;
    int tr = (tid >> 4) * TM, tc = (tid & 15) * TN;
    float acc[TM][TN] = {};
    gemm_mainloop<DD, false>(x, DD, W, DD, bm, bn, acc);
#pragma unroll
    for (int i = 0; i < TM; i++) {
        int row = bm + tr + i;
#pragma unroll
        for (int j = 0; j < TN; j += 4) {
            float4 r;
            r.x = acc[i][j + 0] + bias[bn + tc + j + 0];
            r.y = acc[i][j + 1] + bias[bn + tc + j + 1];
            r.z = acc[i][j + 2] + bias[bn + tc + j + 2];
            r.w = acc[i][j + 3] + bias[bn + tc + j + 3];
            *(float4*)&C[(size_t)row * DD + bn + tc + j] = r;
        }
    }
}

// ---------------- K8: output projection ----------------
__global__ __launch_bounds__(256, 2) void outproj_kernel(
    const float* __restrict__ A, const float* __restrict__ W,
    const float* __restrict__ bias, float* __restrict__ C)
{
    int bm = blockIdx.y * BM, bn = blockIdx.x * BN;
    int tid = threadIdx.x;
    int tr = (tid >> 4) * TM, tc = (tid & 15) * TN;
    float acc[TM][TN] = {};
    gemm_mainloop<DD, false>(A, DD, W, DD, bm, bn, acc);
#pragma unroll
    for (int i = 0; i < TM; i++) {
        int row = bm + tr + i;
#pragma unroll
        for (int j = 0; j < TN; j += 4) {
            float4 r;
            r.x = acc[i][j + 0] + bias[bn + tc + j + 0];
            r.y = acc[i][j + 1] + bias[bn + tc + j + 1];
            r.z = acc[i][j + 2] + bias[bn + tc + j + 2];
            r.w = acc[i][j + 3] + bias[bn + tc + j + 3];
            *(float4*)&C[(size_t)row * DD + bn + tc + j] = r;
        }
    }
}

// ---------------- K2: scores + fused hist + atomic-free window staging -------
__global__ __launch_bounds__(256, 2) void scores_kernel() {
    extern __shared__ unsigned shh[];          // [NBINS] hist (32 KB dynamic)
    __shared__ unsigned wscan[8];
    __shared__ int s_base, s_total;
    int h = blockIdx.z;
    int bm = blockIdx.y * BM, bn = blockIdx.x * BN;
    int tid = threadIdx.x;
    int lane = tid & 31, warp = tid >> 5;
    int tr = (tid >> 4) * TM, tc = (tid & 15) * TN;

    for (int i = tid; i < NBINS; i += 256) shh[i] = 0;

    float acc[TM][TN] = {};
    gemm_mainloop<HDIM, true>(g_q + h * HDIM, DD, g_k + h * HDIM, DD, bm, bn, acc);
    // mainloop ends with __syncthreads(): shh zeroing complete.

    float* out = g_scores + (size_t)h * SS * SS;
    unsigned cnt = 0;                          // window hits this thread
    auto emit = [&](float v) {
        atomicAdd(&shh[score_bin(v)], 1u);
        float s4 = v + 4.0f;
        if (s4 >= WLO_F && s4 < WHI_F) cnt++;
    };
#pragma unroll
    for (int i = 0; i < TM; i++) {
        size_t row = bm + tr + i;
#pragma unroll
        for (int j = 0; j < TN; j += 4) {
            float4 r;
            r.x = acc[i][j + 0] * 0.125f;
            r.y = acc[i][j + 1] * 0.125f;
            r.z = acc[i][j + 2] * 0.125f;
            r.w = acc[i][j + 3] * 0.125f;
            *(float4*)&out[row * SS + bn + tc + j] = r;
            emit(r.x); emit(r.y); emit(r.z); emit(r.w);
        }
    }
    // block exclusive scan of per-thread window counts
    unsigned x = cnt;
#pragma unroll
    for (int o = 1; o < 32; o <<= 1) {
        unsigned y = __shfl_up_sync(0xffffffffu, x, o);
        if (lane >= o) x += y;
    }
    if (lane == 31) wscan[warp] = x;
    __syncthreads();
    if (tid == 0) {
        unsigned c = 0;
        for (int w = 0; w < 8; w++) { unsigned t2 = wscan[w]; wscan[w] = c; c += t2; }
        s_total = (int)c;
        int base = atomicAdd(&g_wcnt[h], (int)c);
        s_base = base;
        if (base + (int)c > WCAP) g_wover[h] = 1;
    }
    __syncthreads();
    // pass 2: re-derive identical values, write hits at base + prefix
    if (s_base + s_total <= WCAP) {
        float* wc = g_wcand + (size_t)h * WCAP;
        int off = s_base + (int)(x - cnt) + (int)wscan[warp];
#pragma unroll
        for (int i = 0; i < TM; i++) {
#pragma unroll
            for (int j = 0; j < TN; j++) {
                float v = acc[i][j] * 0.125f;
                float s4 = v + 4.0f;
                if (s4 >= WLO_F && s4 < WHI_F) wc[off++] = v;
            }
        }
    }
    // publish histogram
    unsigned* gh = g_hist + h * NBINS;
    for (int i = tid; i < NBINS; i += 256) {
        unsigned c = shh[i];
        if (c) atomicAdd(&gh[i], c);
    }
}

// ---------------- inline rank-scan over g_hist -------------------------------
__device__ __forceinline__ void rank_scan_256(
    const unsigned* __restrict__ hh, int tid,
    unsigned* wsum /*[8] shared*/, int* sb0, int* sb1, int* sbase)
{
    const int PER = NBINS / 256;   // 32
    int start = tid * PER;
    unsigned s = 0;
#pragma unroll
    for (int i = 0; i < PER; i++) s += hh[start + i];
    unsigned x = s;
#pragma unroll
    for (int o = 1; o < 32; o <<= 1) {
        unsigned y = __shfl_up_sync(0xffffffffu, x, o);
        if ((tid & 31) >= o) x += y;
    }
    if ((tid & 31) == 31) wsum[tid >> 5] = x;
    __syncthreads();
    if (tid == 0) {
        unsigned c = 0;
        for (int w = 0; w < 8; w++) { unsigned t2 = wsum[w]; wsum[w] = c; c += t2; }
    }
    __syncthreads();
    unsigned c = x - s + wsum[tid >> 5];
    const unsigned I0 = RANK0, I1 = RANK0 + 1;
    for (int i = 0; i < PER; i++) {
        unsigned cnt = hh[start + i];
        if (cnt) {
            if (I0 >= c && I0 < c + cnt) { *sb0 = start + i; *sbase = (int)c; }
            if (I1 >= c && I1 < c + cnt) { *sb1 = start + i; }
        }
        c += cnt;
    }
}

// ---------------- K6: filter window buffer + sort + exact quantile -----------
// One CTA per head. Fast path filters g_wcand (~1 MB); fallback scans g_scores.
// Candidate SET identical to the full-scan test; sort normalizes order.
__global__ __launch_bounds__(1024) void select_kernel() {
    extern __shared__ float sm[];
    __shared__ unsigned wsum[8];
    __shared__ int sb0, sb1, sbase, scnt;
    int h = blockIdx.x;
    int tid = threadIdx.x;
    int lane = tid & 31;
    if (tid == 0) scnt = 0;
    if (tid < 256) rank_scan_256(g_hist + h * NBINS, tid, wsum, &sb0, &sb1, &sbase);
    else { __syncthreads(); __syncthreads(); }
    __syncthreads();
    const float c0 = (float)sb0 * 0.0009765625f;        // B0 / 1024 (exact)
    const float c1 = (float)(sb1 + 1) * 0.0009765625f;  // (B1+1) / 1024 (exact)

    bool fast = (sb0 >= WLO_BIN) && (sb1 < WHI_BIN) && (g_wover[h] == 0)
                && (g_wcnt[h] <= WCAP);

    auto append = [&](float val, bool hit) {
        unsigned bal = __ballot_sync(0xffffffffu, hit);
        if (bal) {
            int wb = 0;
            if (lane == 0) wb = atomicAdd(&scnt, __popc(bal));
            wb = __shfl_sync(0xffffffffu, wb, 0);
            if (hit) {
                int pos = wb + __popc(bal & ((1u << lane) - 1u));
                if (pos < CCAP) sm[pos] = val;
            }
        }
    };

    if (fast) {
        int n = g_wcnt[h];
        const float* wc = g_wcand + (size_t)h * WCAP;
        int nr = (n + 1023) & ~1023;          // uniform trip count for ballots
        for (int i = tid; i < nr; i += 1024) {
            float val = (i < n) ? wc[i] : 0.f;
            float s4 = val + 4.0f;
            bool hit = (i < n) && (s4 >= c0) && (s4 < c1);
            append(val, hit);
        }
    } else {
        const size_t per_head = (size_t)SS * SS;
        const float* base = g_scores + (size_t)h * per_head;
        for (size_t i = tid; i < per_head; i += 1024) {
            float val = __ldcs(&base[i]);
            float s4 = val + 4.0f;
            bool hit = (s4 >= c0) && (s4 < c1);
            append(val, hit);
        }
    }
    __syncthreads();

    int n = min(scnt, CCAP);
    int m = 1024;
    while (m < n) m <<= 1;
    for (int i = n + tid; i < m; i += 1024) sm[i] = inf_f();
    __syncthreads();
    for (int k = 2; k <= m; k <<= 1) {
        for (int j = k >> 1; j > 0; j >>= 1) {
            for (int i = tid; i < m; i += 1024) {
                int ixj = i ^ j;
                if (ixj > i) {
                    bool up = ((i & k) == 0);
                    float a = sm[i], b = sm[ixj];
                    if ((a > b) == up) { sm[i] = b; sm[ixj] = a; }
                }
            }
            __syncthreads();
        }
    }
    if (tid == 0) {
        float idxf = 0.95f * (float)(SS * SS - 1);
        float frac = idxf - floorf(idxf);   // 0.75 in fp32
        int r0 = RANK0 - sbase;
        if (r0 < 0) r0 = 0;
        if (r0 > n - 2) r0 = n - 2;
        float v0 = sm[r0], v1 = sm[r0 + 1];
        g_thr[h] = v0 + frac * (v1 - v0);
    }
}

// ---------------- K7: masked softmax + attn@V, chunked compaction ------------
#define CH 512
__global__ __launch_bounds__(256) void attn_kernel() {
    __shared__ float          sv[8][CH];
    __shared__ unsigned short si[8][CH];
    int h = blockIdx.y;
    int warp = threadIdx.x >> 5;
    int lane = threadIdx.x & 31;
    int row = blockIdx.x * 8 + warp;
    float t = g_thr[h];
    const float* srow = g_scores + ((size_t)h * SS + row) * SS;
    const float* vh = g_v + h * HDIM;
    const float NEG = -inf_f();
    float m = NEG, l = 0.f, acc0 = 0.f, acc1 = 0.f;
    for (int c0 = 0; c0 < SS; c0 += CH) {
        int cnt = 0;
        float lmax = NEG;
#pragma unroll
        for (int cc = 0; cc < CH; cc += 32) {
            float s = __ldcs(&srow[c0 + cc + lane]);
            bool kept = (s >= t);
            unsigned bal = __ballot_sync(0xffffffffu, kept);
            if (kept) {
                int pos = cnt + __popc(bal & ((1u << lane) - 1u));
                sv[warp][pos] = s;
                si[warp][pos] = (unsigned short)(c0 + cc + lane);
                lmax = fmaxf(lmax, s);
            }
            cnt += __popc(bal);
        }
        if (cnt == 0) continue;
#pragma unroll
        for (int o = 16; o; o >>= 1) lmax = fmaxf(lmax, __shfl_xor_sync(0xffffffffu, lmax, o));
        if (lmax > m) {
            float corr = (m == NEG) ? 0.f : __expf(m - lmax);
            l *= corr; acc0 *= corr; acc1 *= corr;
            m = lmax;
        }
        __syncwarp();
        for (int i = lane; i < cnt; i += 32)
            sv[warp][i] = __expf(sv[warp][i] - m);
        __syncwarp();
        int i = 0;
        for (; i + 4 <= cnt; i += 4) {
            float p0 = sv[warp][i + 0], p1 = sv[warp][i + 1];
            float p2 = sv[warp][i + 2], p3 = sv[warp][i + 3];
            const float* v0 = vh + (size_t)si[warp][i + 0] * DD;
            const float* v1 = vh + (size_t)si[warp][i + 1] * DD;
            const float* v2 = vh + (size_t)si[warp][i + 2] * DD;
            const float* v3 = vh + (size_t)si[warp][i + 3] * DD;
            acc0 += p0 * v0[lane]      + p1 * v1[lane]      + p2 * v2[lane]      + p3 * v3[lane];
            acc1 += p0 * v0[lane + 32] + p1 * v1[lane + 32] + p2 * v2[lane + 32] + p3 * v3[lane + 32];
            l += p0 + p1 + p2 + p3;
        }
        for (; i < cnt; ++i) {
            float p = sv[warp][i];
            const float* vr = vh + (size_t)si[warp][i] * DD;
            acc0 += p * vr[lane];
            acc1 += p * vr[lane + 32];
            l += p;
        }
        __syncwarp();
    }
    float inv = (l > 0.f) ? 1.f / l : 0.f;
    g_o[(size_t)row * DD + h * HDIM + lane]      = acc0 * inv;
    g_o[(size_t)row * DD + h * HDIM + lane + 32] = acc1 * inv;
}

// ---------------- launch ----------------
extern "C" void kernel_launch(void* const* d_in, const int* in_sizes, int n_in,
                              void* d_out, int out_size) {
    (void)in_sizes; (void)n_in; (void)out_size;
    const float* x  = (const float*)d_in[0];
    const float* Wq = (const float*)d_in[1];
    const float* bq = (const float*)d_in[2];
    const float* Wk = (const float*)d_in[3];
    const float* bk = (const float*)d_in[4];
    const float* Wv = (const float*)d_in[5];
    const float* bv = (const float*)d_in[6];
    const float* Wo = (const float*)d_in[7];
    const float* bo = (const float*)d_in[8];
    float* out = (float*)d_out;

    cudaFuncSetAttribute(scores_kernel, cudaFuncAttributeMaxDynamicSharedMemorySize, NBINS * 4);
    cudaFuncSetAttribute(select_kernel, cudaFuncAttributeMaxDynamicSharedMemorySize, CCAP * 4);

    float *pq, *pk, *pv, *po;
    cudaGetSymbolAddress((void**)&pq, g_q);
    cudaGetSymbolAddress((void**)&pk, g_k);
    cudaGetSymbolAddress((void**)&pv, g_v);
    cudaGetSymbolAddress((void**)&po, g_o);

    zero_kernel<<<(NH * NBINS + 255) / 256, 256>>>();
    qkv_kernel<<<dim3(DD / BN, SS / BM, 3), 256>>>(x, Wq, bq, Wk, bk, Wv, bv, pq, pk, pv);
    scores_kernel<<<dim3(SS / BN, SS / BM, NH), 256, NBINS * 4>>>();
    select_kernel<<<NH, 1024, CCAP * 4>>>();
    attn_kernel<<<dim3(SS / 8, NH), 256>>>();
    outproj_kernel<<<dim3(DD / BN, SS / BM), 256>>>(po, Wo, bo, out);
}

// round 17
// speedup vs baseline: 1.1167x; 1.1167x over previous
#include <cuda_runtime.h>
#include <cstdint>

#define SS   2048
#define DD   1024
#define NH   16
#define HDIM 64
#define NBINS 8192
#define CCAP  32768
#define RANK0 3984587

// candidate window: bins [WLO_BIN, WHI_BIN) ~ scores in [0.55, 0.80)
#define WLO_BIN 4659
#define WHI_BIN 4916
#define WLO_F   (WLO_BIN * 0.0009765625f)   // exact fp32
#define WHI_F   (WHI_BIN * 0.0009765625f)   // exact fp32
#define WCAP    524288                       // per-head global window buffer cap

#define BM 128
#define BN 128
#define BK 16
#define TM 8
#define TN 8

// ---------------- scratch ----------------
__device__ float g_q[SS * DD];
__device__ float g_k[SS * DD];
__device__ float g_v[SS * DD];
__device__ float g_o[SS * DD];
__device__ float g_scores[(size_t)NH * SS * SS];   // 256 MB
__device__ unsigned g_hist[NH * NBINS];
__device__ float g_cand[NH * CCAP];
__device__ int g_cnt[NH];
__device__ float g_thr[NH];
__device__ float g_wcand[(size_t)NH * WCAP];       // 32 MB window buffer
__device__ int g_wcnt[NH];
__device__ int g_wover[NH];

__device__ __forceinline__ float inf_f() { return __int_as_float(0x7f800000); }

// 8192 bins over [-4,4): width 1/1024; x1024 exact, so the bin test is an
// exact fp32 interval test on fl(v+4).
__device__ __forceinline__ int score_bin(float v) {
    int b = __float2int_rd((v + 4.0f) * 1024.0f);
    return min(max(b, 0), NBINS - 1);
}

// ---------------- K0: zero per-launch state ----------------
__global__ void zero_kernel() {
    int i = blockIdx.x * blockDim.x + threadIdx.x;
    if (i < NH * NBINS) g_hist[i] = 0;
    if (i < NH) { g_cnt[i] = 0; g_wcnt[i] = 0; g_wover[i] = 0; }
}

// ---------------- double-buffered fp32 GEMM mainloop ----------------
template<int KTOT, bool BT>
__device__ __forceinline__ void gemm_mainloop(
    const float* __restrict__ A, int lda,
    const float* __restrict__ Bm, int ldb,
    int bm, int bn, float acc[TM][TN])
{
    __shared__ float As[2][BK][BM];
    __shared__ float Bs[2][BK][BN];
    const int tid = threadIdx.x;
    const int tr = (tid >> 4) * TM;
    const int tc = (tid & 15) * TN;

    const int ar0 = tid >> 2;           // 0..63
    const int ar1 = ar0 + 64;           // 64..127
    const int ac  = (tid & 3) * 4;      // 0,4,8,12
    const int br0 = tid >> 5;           // 0..7
    const int br1 = br0 + 8;
    const int bc  = (tid & 31) * 4;

    float4 pa0, pa1, pb0, pb1;

    auto loadT = [&](int k0) {
        pa0 = *(const float4*)&A[(size_t)(bm + ar0) * lda + k0 + ac];
        pa1 = *(const float4*)&A[(size_t)(bm + ar1) * lda + k0 + ac];
        if (BT) {
            pb0 = *(const float4*)&Bm[(size_t)(bn + ar0) * ldb + k0 + ac];
            pb1 = *(const float4*)&Bm[(size_t)(bn + ar1) * ldb + k0 + ac];
        } else {
            pb0 = *(const float4*)&Bm[(size_t)(k0 + br0) * ldb + bn + bc];
            pb1 = *(const float4*)&Bm[(size_t)(k0 + br1) * ldb + bn + bc];
        }
    };
    auto storeT = [&](int buf) {
        As[buf][ac + 0][ar0] = pa0.x; As[buf][ac + 1][ar0] = pa0.y;
        As[buf][ac + 2][ar0] = pa0.z; As[buf][ac + 3][ar0] = pa0.w;
        As[buf][ac + 0][ar1] = pa1.x; As[buf][ac + 1][ar1] = pa1.y;
        As[buf][ac + 2][ar1] = pa1.z; As[buf][ac + 3][ar1] = pa1.w;
        if (BT) {
            Bs[buf][ac + 0][ar0] = pb0.x; Bs[buf][ac + 1][ar0] = pb0.y;
            Bs[buf][ac + 2][ar0] = pb0.z; Bs[buf][ac + 3][ar0] = pb0.w;
            Bs[buf][ac + 0][ar1] = pb1.x; Bs[buf][ac + 1][ar1] = pb1.y;
            Bs[buf][ac + 2][ar1] = pb1.z; Bs[buf][ac + 3][ar1] = pb1.w;
        } else {
            *(float4*)&Bs[buf][br0][bc] = pb0;
            *(float4*)&Bs[buf][br1][bc] = pb1;
        }
    };

    loadT(0);
    storeT(0);
    __syncthreads();
    const int NIT = KTOT / BK;
    for (int it = 0; it < NIT; ++it) {
        int buf = it & 1;
        if (it + 1 < NIT) loadT((it + 1) * BK);
#pragma unroll
        for (int kk = 0; kk < BK; ++kk) {
            float4 a0 = *(const float4*)&As[buf][kk][tr];
            float4 a1 = *(const float4*)&As[buf][kk][tr + 4];
            float4 b0 = *(const float4*)&Bs[buf][kk][tc];
            float4 b1 = *(const float4*)&Bs[buf][kk][tc + 4];
            float af[TM] = {a0.x, a0.y, a0.z, a0.w, a1.x, a1.y, a1.z, a1.w};
            float bf[TN] = {b0.x, b0.y, b0.z, b0.w, b1.x, b1.y, b1.z, b1.w};
#pragma unroll
            for (int i = 0; i < TM; i++)
#pragma unroll
                for (int j = 0; j < TN; j++)
                    acc[i][j] += af[i] * bf[j];
        }
        if (it + 1 < NIT) storeT(buf ^ 1);
        __syncthreads();
    }
}

// ---------------- K1: fused QKV projection ----------------
__global__ __launch_bounds__(256, 2) void qkv_kernel(
    const float* __restrict__ x,
    const float* __restrict__ Wq, const float* __restrict__ bq,
    const float* __restrict__ Wk, const float* __restrict__ bk,
    const float* __restrict__ Wv, const float* __restrict__ bv,
    float* __restrict__ q, float* __restrict__ k, float* __restrict__ v)
{
    const float* W; const float* bias; float* C;
    if (blockIdx.z == 0)      { W = Wq; bias = bq; C = q; }
    else if (blockIdx.z == 1) { W = Wk; bias = bk; C = k; }
    else                      { W = Wv; bias = bv; C = v; }

    int bm = blockIdx.y * BM, bn = blockIdx.x * BN;
    int tid = threadIdx.x;
    int tr = (tid >> 4) * TM, tc = (tid & 15) * TN;
    float acc[TM][TN] = {};
    gemm_mainloop<DD, false>(x, DD, W, DD, bm, bn, acc);
#pragma unroll
    for (int i = 0; i < TM; i++) {
        int row = bm + tr + i;
#pragma unroll
        for (int j = 0; j < TN; j += 4) {
            float4 r;
            r.x = acc[i][j + 0] + bias[bn + tc + j + 0];
            r.y = acc[i][j + 1] + bias[bn + tc + j + 1];
            r.z = acc[i][j + 2] + bias[bn + tc + j + 2];
            r.w = acc[i][j + 3] + bias[bn + tc + j + 3];
            *(float4*)&C[(size_t)row * DD + bn + tc + j] = r;
        }
    }
}

// ---------------- K8: output projection ----------------
__global__ __launch_bounds__(256, 2) void outproj_kernel(
    const float* __restrict__ A, const float* __restrict__ W,
    const float* __restrict__ bias, float* __restrict__ C)
{
    int bm = blockIdx.y * BM, bn = blockIdx.x * BN;
    int tid = threadIdx.x;
    int tr = (tid >> 4) * TM, tc = (tid & 15) * TN;
    float acc[TM][TN] = {};
    gemm_mainloop<DD, false>(A, DD, W, DD, bm, bn, acc);
#pragma unroll
    for (int i = 0; i < TM; i++) {
        int row = bm + tr + i;
#pragma unroll
        for (int j = 0; j < TN; j += 4) {
            float4 r;
            r.x = acc[i][j + 0] + bias[bn + tc + j + 0];
            r.y = acc[i][j + 1] + bias[bn + tc + j + 1];
            r.z = acc[i][j + 2] + bias[bn + tc + j + 2];
            r.w = acc[i][j + 3] + bias[bn + tc + j + 3];
            *(float4*)&C[(size_t)row * DD + bn + tc + j] = r;
        }
    }
}

// ---------------- K2: scores + fused hist + atomic-free window staging -------
__global__ __launch_bounds__(256, 2) void scores_kernel() {
    extern __shared__ unsigned shh[];          // [NBINS] hist (32 KB dynamic)
    __shared__ unsigned wscan[8];
    __shared__ int s_base, s_total;
    int h = blockIdx.z;
    int bm = blockIdx.y * BM, bn = blockIdx.x * BN;
    int tid = threadIdx.x;
    int lane = tid & 31, warp = tid >> 5;
    int tr = (tid >> 4) * TM, tc = (tid & 15) * TN;

    for (int i = tid; i < NBINS; i += 256) shh[i] = 0;

    float acc[TM][TN] = {};
    gemm_mainloop<HDIM, true>(g_q + h * HDIM, DD, g_k + h * HDIM, DD, bm, bn, acc);
    // mainloop ends with __syncthreads(): shh zeroing complete.

    float* out = g_scores + (size_t)h * SS * SS;
    unsigned cnt = 0;                          // window hits this thread
    auto emit = [&](float v) {
        atomicAdd(&shh[score_bin(v)], 1u);
        float s4 = v + 4.0f;
        if (s4 >= WLO_F && s4 < WHI_F) cnt++;
    };
#pragma unroll
    for (int i = 0; i < TM; i++) {
        size_t row = bm + tr + i;
#pragma unroll
        for (int j = 0; j < TN; j += 4) {
            float4 r;
            r.x = acc[i][j + 0] * 0.125f;
            r.y = acc[i][j + 1] * 0.125f;
            r.z = acc[i][j + 2] * 0.125f;
            r.w = acc[i][j + 3] * 0.125f;
            *(float4*)&out[row * SS + bn + tc + j] = r;
            emit(r.x); emit(r.y); emit(r.z); emit(r.w);
        }
    }
    // block exclusive scan of per-thread window counts (no shared atomics)
    unsigned x = cnt;
#pragma unroll
    for (int o = 1; o < 32; o <<= 1) {
        unsigned y = __shfl_up_sync(0xffffffffu, x, o);
        if (lane >= o) x += y;
    }
    if (lane == 31) wscan[warp] = x;
    __syncthreads();
    if (tid == 0) {
        unsigned c = 0;
        for (int w = 0; w < 8; w++) { unsigned t2 = wscan[w]; wscan[w] = c; c += t2; }
        s_total = (int)c;
        int base = atomicAdd(&g_wcnt[h], (int)c);
        s_base = base;
        if (base + (int)c > WCAP) g_wover[h] = 1;
    }
    __syncthreads();
    // pass 2: re-derive identical values, write hits at base + prefix
    if (s_base + s_total <= WCAP) {
        float* wc = g_wcand + (size_t)h * WCAP;
        int off = s_base + (int)(x - cnt) + (int)wscan[warp];
#pragma unroll
        for (int i = 0; i < TM; i++) {
#pragma unroll
            for (int j = 0; j < TN; j++) {
                float v = acc[i][j] * 0.125f;
                float s4 = v + 4.0f;
                if (s4 >= WLO_F && s4 < WHI_F) wc[off++] = v;
            }
        }
    }
    // publish histogram
    unsigned* gh = g_hist + h * NBINS;
    for (int i = tid; i < NBINS; i += 256) {
        unsigned c = shh[i];
        if (c) atomicAdd(&gh[i], c);
    }
}

// ---------------- rank-scan over g_hist (uint4 loads, threads [0,256)) -------
__device__ __forceinline__ void rank_scan_256(
    const unsigned* __restrict__ hh, int tid,
    unsigned* wsum /*[8] shared*/, int* sb0, int* sb1, int* sbase)
{
    const uint4* h4 = (const uint4*)hh;    // 2048 uint4 per head (32KB aligned)
    uint4 v[8];
#pragma unroll
    for (int i = 0; i < 8; i++) v[i] = h4[tid * 8 + i];
    unsigned s = 0;
#pragma unroll
    for (int i = 0; i < 8; i++) s += v[i].x + v[i].y + v[i].z + v[i].w;
    unsigned x = s;
#pragma unroll
    for (int o = 1; o < 32; o <<= 1) {
        unsigned y = __shfl_up_sync(0xffffffffu, x, o);
        if ((tid & 31) >= o) x += y;
    }
    if ((tid & 31) == 31) wsum[tid >> 5] = x;
    __syncthreads();
    if (tid == 0) {
        unsigned c = 0;
        for (int w = 0; w < 8; w++) { unsigned t2 = wsum[w]; wsum[w] = c; c += t2; }
    }
    __syncthreads();
    unsigned c = x - s + wsum[tid >> 5];
    const unsigned I0 = RANK0, I1 = RANK0 + 1;
    int start = tid * 32;
#pragma unroll
    for (int i = 0; i < 8; i++) {
        unsigned q[4] = {v[i].x, v[i].y, v[i].z, v[i].w};
#pragma unroll
        for (int t = 0; t < 4; t++) {
            unsigned cnt = q[t];
            if (cnt) {
                int b = start + i * 4 + t;
                if (I0 >= c && I0 < c + cnt) { *sb0 = b; *sbase = (int)c; }
                if (I1 >= c && I1 < c + cnt) { *sb1 = b; }
            }
            c += cnt;
        }
    }
}

// ---------------- K5: candidates (windowed fast path; full-scan fallback) ----
__global__ __launch_bounds__(1024) void candidates_kernel() {
    __shared__ unsigned wsum[8];
    __shared__ int sb0, sb1, sbase;
    int h = blockIdx.y;
    int tid = threadIdx.x;
    int lane = tid & 31;
    if (tid < 256) rank_scan_256(g_hist + h * NBINS, tid, wsum, &sb0, &sb1, &sbase);
    else { __syncthreads(); __syncthreads(); }   // match barriers inside
    __syncthreads();
    const float c0 = (float)sb0 * 0.0009765625f;        // B0 / 1024 (exact)
    const float c1 = (float)(sb1 + 1) * 0.0009765625f;  // (B1+1) / 1024 (exact)

    bool fast = (sb0 >= WLO_BIN) && (sb1 < WHI_BIN) && (g_wover[h] == 0)
                && (g_wcnt[h] <= WCAP);

    auto append = [&](float val, bool hit) {
        unsigned bal = __ballot_sync(0xffffffffu, hit);
        if (bal) {
            int wb = 0;
            if (lane == 0) wb = atomicAdd(&g_cnt[h], __popc(bal));
            wb = __shfl_sync(0xffffffffu, wb, 0);
            if (hit) {
                int pos = wb + __popc(bal & ((1u << lane) - 1u));
                if (pos < CCAP) g_cand[h * CCAP + pos] = val;
            }
        }
    };

    if (fast) {
        int n = g_wcnt[h];
        const float4* wc4 = (const float4*)(g_wcand + (size_t)h * WCAP);
        int n4 = n >> 2;
        int stride = gridDim.x * blockDim.x;   // 32768
        int nr4 = (n4 + stride - 1) / stride * stride;   // uniform trips
        for (int i = blockIdx.x * blockDim.x + tid; i < nr4; i += stride) {
            float4 v = (i < n4) ? __ldcs(&wc4[i]) : make_float4(0, 0, 0, 0);
#pragma unroll
            for (int t = 0; t < 4; t++) {
                float val = (&v.x)[t];
                float s4 = val + 4.0f;
                bool hit = (i < n4) && (s4 >= c0) && (s4 < c1);
                append(val, hit);
            }
        }
        // tail (n % 4 values) handled by first warp of block 0
        if (blockIdx.x == 0 && tid < 32) {
            int base = n4 << 2;
            float val = 0.f; bool hit = false;
            if (base + lane < n) {
                val = g_wcand[(size_t)h * WCAP + base + lane];
                float s4 = val + 4.0f;
                hit = (s4 >= c0) && (s4 < c1);
            }
            append(val, hit);
        }
    } else {
        const size_t per_head = (size_t)SS * SS;
        const float4* base = (const float4*)(g_scores + (size_t)h * per_head);
        const size_t n4 = per_head / 4;
        const size_t stride = (size_t)gridDim.x * blockDim.x;
        size_t idx = (size_t)blockIdx.x * blockDim.x + tid;
        for (size_t i = idx; i < n4; i += 4 * stride) {
            float4 v0 = __ldcs(&base[i]);
            float4 v1 = __ldcs(&base[i + stride]);
            float4 v2 = __ldcs(&base[i + 2 * stride]);
            float4 v3 = __ldcs(&base[i + 3 * stride]);
            float4 vs[4] = {v0, v1, v2, v3};
#pragma unroll
            for (int b = 0; b < 4; b++)
#pragma unroll
                for (int t = 0; t < 4; t++) {
                    float val = (&vs[b].x)[t];
                    float s4 = val + 4.0f;
                    if (s4 >= c0 && s4 < c1) {
                        int p = atomicAdd(&g_cnt[h], 1);
                        if (p < CCAP) g_cand[h * CCAP + p] = val;
                    }
                }
        }
    }
}

// ---------------- K6: sort candidates, exact quantile ------------------------
__global__ __launch_bounds__(1024) void select_kernel() {
    extern __shared__ float sm[];
    __shared__ unsigned wsum[8];
    __shared__ int sb0, sb1, sbase;
    int h = blockIdx.x;
    int tid = threadIdx.x;
    if (tid < 256) rank_scan_256(g_hist + h * NBINS, tid, wsum, &sb0, &sb1, &sbase);
    else { __syncthreads(); __syncthreads(); }
    __syncthreads();

    int n = min(g_cnt[h], CCAP);
    int m = 1024;
    while (m < n) m <<= 1;
    for (int i = tid; i < m; i += 1024)
        sm[i] = (i < n) ? g_cand[h * CCAP + i] : inf_f();
    __syncthreads();
    for (int k = 2; k <= m; k <<= 1) {
        for (int j = k >> 1; j > 0; j >>= 1) {
            for (int i = tid; i < m; i += 1024) {
                int ixj = i ^ j;
                if (ixj > i) {
                    bool up = ((i & k) == 0);
                    float a = sm[i], b = sm[ixj];
                    if ((a > b) == up) { sm[i] = b; sm[ixj] = a; }
                }
            }
            __syncthreads();
        }
    }
    if (tid == 0) {
        float idxf = 0.95f * (float)(SS * SS - 1);
        float frac = idxf - floorf(idxf);   // 0.75 in fp32
        int r0 = RANK0 - sbase;
        if (r0 < 0) r0 = 0;
        if (r0 > n - 2) r0 = n - 2;
        float v0 = sm[r0], v1 = sm[r0 + 1];
        g_thr[h] = v0 + frac * (v1 - v0);
    }
}

// ---------------- K7: masked softmax + attn@V, chunked compaction ------------
#define CH 512
__global__ __launch_bounds__(256) void attn_kernel() {
    __shared__ float          sv[8][CH];
    __shared__ unsigned short si[8][CH];
    int h = blockIdx.y;
    int warp = threadIdx.x >> 5;
    int lane = threadIdx.x & 31;
    int row = blockIdx.x * 8 + warp;
    float t = g_thr[h];
    const float* srow = g_scores + ((size_t)h * SS + row) * SS;
    const float* vh = g_v + h * HDIM;
    const float NEG = -inf_f();
    float m = NEG, l = 0.f, acc0 = 0.f, acc1 = 0.f;
    for (int c0 = 0; c0 < SS; c0 += CH) {
        int cnt = 0;
        float lmax = NEG;
#pragma unroll
        for (int cc = 0; cc < CH; cc += 32) {
            float s = __ldcs(&srow[c0 + cc + lane]);
            bool kept = (s >= t);
            unsigned bal = __ballot_sync(0xffffffffu, kept);
            if (kept) {
                int pos = cnt + __popc(bal & ((1u << lane) - 1u));
                sv[warp][pos] = s;
                si[warp][pos] = (unsigned short)(c0 + cc + lane);
                lmax = fmaxf(lmax, s);
            }
            cnt += __popc(bal);
        }
        if (cnt == 0) continue;
#pragma unroll
        for (int o = 16; o; o >>= 1) lmax = fmaxf(lmax, __shfl_xor_sync(0xffffffffu, lmax, o));
        if (lmax > m) {
            float corr = (m == NEG) ? 0.f : __expf(m - lmax);
            l *= corr; acc0 *= corr; acc1 *= corr;
            m = lmax;
        }
        __syncwarp();
        for (int i = lane; i < cnt; i += 32)
            sv[warp][i] = __expf(sv[warp][i] - m);
        __syncwarp();
        int i = 0;
        for (; i + 4 <= cnt; i += 4) {
            float p0 = sv[warp][i + 0], p1 = sv[warp][i + 1];
            float p2 = sv[warp][i + 2], p3 = sv[warp][i + 3];
            const float* v0 = vh + (size_t)si[warp][i + 0] * DD;
            const float* v1 = vh + (size_t)si[warp][i + 1] * DD;
            const float* v2 = vh + (size_t)si[warp][i + 2] * DD;
            const float* v3 = vh + (size_t)si[warp][i + 3] * DD;
            acc0 += p0 * v0[lane]      + p1 * v1[lane]      + p2 * v2[lane]      + p3 * v3[lane];
            acc1 += p0 * v0[lane + 32] + p1 * v1[lane + 32] + p2 * v2[lane + 32] + p3 * v3[lane + 32];
            l += p0 + p1 + p2 + p3;
        }
        for (; i < cnt; ++i) {
            float p = sv[warp][i];
            const float* vr = vh + (size_t)si[warp][i] * DD;
            acc0 += p * vr[lane];
            acc1 += p * vr[lane + 32];
            l += p;
        }
        __syncwarp();
    }
    float inv = (l > 0.f) ? 1.f / l : 0.f;
    g_o[(size_t)row * DD + h * HDIM + lane]      = acc0 * inv;
    g_o[(size_t)row * DD + h * HDIM + lane + 32] = acc1 * inv;
}

// ---------------- launch ----------------
extern "C" void kernel_launch(void* const* d_in, const int* in_sizes, int n_in,
                              void* d_out, int out_size) {
    (void)in_sizes; (void)n_in; (void)out_size;
    const float* x  = (const float*)d_in[0];
    const float* Wq = (const float*)d_in[1];
    const float* bq = (const float*)d_in[2];
    const float* Wk = (const float*)d_in[3];
    const float* bk = (const float*)d_in[4];
    const float* Wv = (const float*)d_in[5];
    const float* bv = (const float*)d_in[6];
    const float* Wo = (const float*)d_in[7];
    const float* bo = (const float*)d_in[8];
    float* out = (float*)d_out;

    cudaFuncSetAttribute(scores_kernel, cudaFuncAttributeMaxDynamicSharedMemorySize, NBINS * 4);
    cudaFuncSetAttribute(select_kernel, cudaFuncAttributeMaxDynamicSharedMemorySize, CCAP * 4);

    float *pq, *pk, *pv, *po;
    cudaGetSymbolAddress((void**)&pq, g_q);
    cudaGetSymbolAddress((void**)&pk, g_k);
    cudaGetSymbolAddress((void**)&pv, g_v);
    cudaGetSymbolAddress((void**)&po, g_o);

    zero_kernel<<<(NH * NBINS + 255) / 256, 256>>>();
    qkv_kernel<<<dim3(DD / BN, SS / BM, 3), 256>>>(x, Wq, bq, Wk, bk, Wv, bv, pq, pk, pv);
    scores_kernel<<<dim3(SS / BN, SS / BM, NH), 256, NBINS * 4>>>();
    candidates_kernel<<<dim3(32, NH), 1024>>>();
    select_kernel<<<NH, 1024, CCAP * 4>>>();
    attn_kernel<<<dim3(SS / 8, NH), 256>>>();
    outproj_kernel<<<dim3(DD / BN, SS / BM), 256>>>(po, Wo, bo, out);
}